// round 10
// baseline (speedup 1.0000x reference)
#include <cuda_runtime.h>
#include <cuda_fp16.h>
#include <cstdint>

// ImageWarped: trilinear sampling of [B,128,128,128,1] fp32 at [B,N,3] coords.
// B=2, N=2097152.
//
// Sample phase is at the L1tex within-LDG replay floor (~30us for both
// batches): 131K warp-gathers x 32 wavefronts x 2.07cyc / 148 SM. This round
// recovers time elsewhere:
//  - x-pair pack: one thread packs voxels (2x',y,z),(2x'+1,y,z), sharing the
//    middle x-plane -> 12 loads + 2 coalesced STG.128 per 2 voxels.
//  - cross-batch overlap, INTERLEAVED: mid kernel alternates pack(b1) and
//    sample(b0) blocks by blockIdx parity so every wave carries both
//    (R6 failed because pack blocks owned the first waves).
// Launches: K1 pack(b0) -> K2 mid -> K3 sample(b1).
//
// fp16 quantization -> rel_err ~2.1e-4 (< 1e-3 gate, verified R3-R9).
// Out-of-range "+1" neighbors are weight-masked (exactly-zero fractional
// weights per the reference floor/ceil convention).

#define BATCH 2
#define NPTS  2097152
#define HVOX  (128 * 128 * 128)            // voxels per batch
#define VOXELS (BATCH * HVOX)
#define CLAMP_LO 0.001f
#define CLAMP_HI 126.999f

#define PACK_PAIR_BLOCKS   (HVOX / 2 / 256)   // 4096 (x-pair, per batch)
#define SAMPLE_BLOCKS      (NPTS / 2 / 256)   // 4096 (2 samples/thread, per batch)

__device__ uint4 g_packed[VOXELS];            // 64 MB scratch

__device__ __forceinline__ uint32_t pack_h2(float a, float b) {
    __half2 h = __floats2half2_rn(a, b);
    return *reinterpret_cast<uint32_t*>(&h);
}

__device__ __forceinline__ uint64_t mk_evict_last_policy() {
    uint64_t pol;
    asm("createpolicy.fractional.L2::evict_last.b64 %0, 1.0;" : "=l"(pol));
    return pol;
}

__device__ __forceinline__ void st_hint_v4(uint4* p, uint4 v, uint64_t pol) {
    asm volatile("st.global.L2::cache_hint.v4.b32 [%0], {%1,%2,%3,%4}, %5;"
                 :: "l"(p), "r"(v.x), "r"(v.y), "r"(v.z), "r"(v.w), "l"(pol)
                 : "memory");
}

__device__ __forceinline__ uint4 ld_nc_hint_v4(const uint4* p, uint64_t pol) {
    uint4 v;
    asm volatile("ld.global.nc.L2::cache_hint.v4.b32 {%0,%1,%2,%3}, [%4], %5;"
                 : "=r"(v.x), "=r"(v.y), "=r"(v.z), "=r"(v.w)
                 : "l"(p), "l"(pol));
    return v;
}

// Pack two x-adjacent voxels (2x', y, z) and (2x'+1, y, z).
// pair_id in [0, HVOX/2); vbase = 0 or HVOX (batch offset).
__device__ __forceinline__ void pack_pair(const float* __restrict__ image,
                                          int pair_id, int vbase, uint64_t pol)
{
    const int xp = pair_id >> 14;           // x' in [0,64)
    const int r  = pair_id & 16383;         // (y<<7)+z
    const int y  = r >> 7;
    const int z  = r & 127;
    const int dz = (z < 127) ? 1 : 0;
    const int dy = (y < 127) ? 128 : 0;

    const int p0 = vbase + (xp << 15) + r;          // plane 2x',   at (y,z)
    const int p1 = p0 + 16384;                      // plane 2x'+1
    const int p2 = (xp < 63) ? p1 + 16384 : p1;     // plane 2x'+2 (clamped)

    // 4 corners per plane: (y,z),(y,z+1),(y+1,z),(y+1,z+1)
    const float a0 = __ldg(image + p0);
    const float b0 = __ldg(image + p0 + dz);
    const float c0 = __ldg(image + p0 + dy);
    const float d0 = __ldg(image + p0 + dy + dz);

    const float a1 = __ldg(image + p1);
    const float b1 = __ldg(image + p1 + dz);
    const float c1 = __ldg(image + p1 + dy);
    const float d1 = __ldg(image + p1 + dy + dz);

    const float a2 = __ldg(image + p2);
    const float b2 = __ldg(image + p2 + dz);
    const float c2 = __ldg(image + p2 + dy);
    const float d2 = __ldg(image + p2 + dy + dz);

    uint4 q0, q1;
    q0.x = pack_h2(a0, b0);   // c111,c112   (x-plane lo)
    q0.y = pack_h2(c0, d0);   // c121,c122
    q0.z = pack_h2(a1, b1);   // c211,c212   (x-plane hi)
    q0.w = pack_h2(c1, d1);   // c221,c222

    q1.x = pack_h2(a1, b1);
    q1.y = pack_h2(c1, d1);
    q1.z = pack_h2(a2, b2);
    q1.w = pack_h2(c2, d2);

    st_hint_v4(&g_packed[p0], q0, pol);     // both coalesced across the warp
    st_hint_v4(&g_packed[p1], q1, pol);
}

__device__ __forceinline__ float sample_one(float gx, float gy, float gz,
                                            int base_b, uint64_t pol)
{
    const float x = fminf(fmaxf(gx * 128.0f, CLAMP_LO), CLAMP_HI);
    const float y = fminf(fmaxf(gy * 128.0f, CLAMP_LO), CLAMP_HI);
    const float z = fminf(fmaxf(gz * 128.0f, CLAMP_LO), CLAMP_HI);

    const float x1f = floorf(x), x2f = ceilf(x);
    const float y1f = floorf(y), y2f = ceilf(y);
    const float z1f = floorf(z), z2f = ceilf(z);

    const int cube = base_b + (((int)x1f) << 14) + (((int)y1f) << 7) + (int)z1f;
    const uint4 p = ld_nc_hint_v4(&g_packed[cube], pol);

    const float2 a1 = __half22float2(*reinterpret_cast<const __half2*>(&p.x)); // c111,c112
    const float2 a2 = __half22float2(*reinterpret_cast<const __half2*>(&p.y)); // c121,c122
    const float2 b1 = __half22float2(*reinterpret_cast<const __half2*>(&p.z)); // c211,c212
    const float2 b2 = __half22float2(*reinterpret_cast<const __half2*>(&p.w)); // c221,c222

    const float wx = x - x1f, wx2 = x2f - x;
    const float wy = y - y1f, wy2 = y2f - y;
    const float wz = z - z1f, wz2 = z2f - z;

    const float lerp_y1 = (b1.x * wx + a1.x * wx2) * wy2
                        + (b2.x * wx + a2.x * wx2) * wy;
    const float lerp_y2 = (b1.y * wx + a1.y * wx2) * wy2
                        + (b2.y * wx + a2.y * wx2) * wy;
    return lerp_y2 * wz + lerp_y1 * wz2;
}

// tprime in [0, NPTS/2); sample_base = 0 or NPTS; base_b = 0 or HVOX.
__device__ __forceinline__ void sample_pair(const float* __restrict__ grid,
                                            float* __restrict__ out,
                                            int tprime, int sample_base,
                                            int base_b, uint64_t pol)
{
    const int s = sample_base + (tprime << 1);
    const float2* g = (const float2*)(grid + 3 * (size_t)s);
    const float2 q0 = __ldcs(g + 0);   // x0 y0
    const float2 q1 = __ldcs(g + 1);   // z0 x1
    const float2 q2 = __ldcs(g + 2);   // y1 z1

    float2 r;
    r.x = sample_one(q0.x, q0.y, q1.x, base_b, pol);
    r.y = sample_one(q1.y, q2.x, q2.y, base_b, pol);
    __stcs((float2*)(out + s), r);
}

__global__ void __launch_bounds__(256)
pack0_kernel(const float* __restrict__ image)
{
    const uint64_t pol = mk_evict_last_policy();
    pack_pair(image, blockIdx.x * 256 + threadIdx.x, 0, pol);        // batch 0
}

// Interleaved: even blocks sample batch0, odd blocks pack batch1.
__global__ void __launch_bounds__(256)
mid_kernel(const float* __restrict__ image,
           const float* __restrict__ grid,
           float* __restrict__ out)
{
    const uint64_t pol = mk_evict_last_policy();
    const int half = blockIdx.x >> 1;
    if (blockIdx.x & 1) {
        pack_pair(image, half * 256 + threadIdx.x, HVOX, pol);       // batch 1
    } else {
        sample_pair(grid, out, half * 256 + threadIdx.x, 0, 0, pol); // batch 0
    }
}

__global__ void __launch_bounds__(256)
sample1_kernel(const float* __restrict__ grid,
               float* __restrict__ out)
{
    const uint64_t pol = mk_evict_last_policy();
    const int tprime = blockIdx.x * 256 + threadIdx.x;
    sample_pair(grid, out, tprime, NPTS, HVOX, pol);                 // batch 1
}

extern "C" void kernel_launch(void* const* d_in, const int* in_sizes, int n_in,
                              void* d_out, int out_size)
{
    const float* image = (const float*)d_in[0];
    const float* grid  = (const float*)d_in[1];
    float* out = (float*)d_out;

    pack0_kernel<<<PACK_PAIR_BLOCKS, 256>>>(image);
    mid_kernel<<<PACK_PAIR_BLOCKS + SAMPLE_BLOCKS, 256>>>(image, grid, out);
    sample1_kernel<<<SAMPLE_BLOCKS, 256>>>(grid, out);
}